// round 2
// baseline (speedup 1.0000x reference)
#include <cuda_runtime.h>
#include <math.h>

#define D 690
#define R 53
#define D2 (D/2)          // 345 float2 per row (690 even -> 8B aligned rows)
#define MAXC 2048         // max rows per bag we buffer (actual max ~100)

// 69 MB scratch for attention-pooled bag representations
__device__ float g_att[25000 * D];

// ---------------------------------------------------------------------------
// Kernel 1: one CTA per bag.
//  Phase A: rel_logits per row (warp-per-row dot with relation_mat[label])
//  Phase B: bag softmax (max, exp, sum)
//  Phase C: att[b] = (1/S) * sum e_i * repre[i]   (rows re-read -> L1/L2 hot)
// ---------------------------------------------------------------------------
__global__ __launch_bounds__(256)
void bag_att_kernel(const float* __restrict__ repre,
                    const float* __restrict__ rel,
                    const int* __restrict__ scope,
                    const int* __restrict__ labels,
                    float* __restrict__ att_out)
{
    __shared__ float s_log[MAXC];
    __shared__ float s_red[8];
    __shared__ float s_bcast;

    const int b   = blockIdx.x;
    const int tid = threadIdx.x;
    const int wid = tid >> 5;
    const int lane = tid & 31;

    const int start = scope[2 * b];
    const int end   = scope[2 * b + 1];
    int cnt = end - start;
    if (cnt > MAXC) cnt = MAXC;   // safety clamp (never hit for this dataset)

    // -------- Phase A: per-row relation logits --------
    for (int row = wid; row < cnt; row += 8) {
        const int i = start + row;
        const float2* rp2 = (const float2*)(repre + (size_t)i * D);
        const float2* rv2 = (const float2*)(rel + (size_t)labels[i] * D);
        float acc = 0.f;
        #pragma unroll 4
        for (int j = lane; j < D2; j += 32) {
            float2 a = rp2[j];
            float2 v = rv2[j];
            acc = fmaf(a.x, v.x, acc);
            acc = fmaf(a.y, v.y, acc);
        }
        #pragma unroll
        for (int o = 16; o; o >>= 1)
            acc += __shfl_xor_sync(0xffffffffu, acc, o);
        if (lane == 0) s_log[row] = acc;
    }
    __syncthreads();

    // -------- Phase B: softmax over the bag --------
    // block max
    float m = -INFINITY;
    for (int idx = tid; idx < cnt; idx += 256) m = fmaxf(m, s_log[idx]);
    #pragma unroll
    for (int o = 16; o; o >>= 1) m = fmaxf(m, __shfl_xor_sync(0xffffffffu, m, o));
    if (lane == 0) s_red[wid] = m;
    __syncthreads();
    if (tid < 32) {
        float v = (tid < 8) ? s_red[tid] : -INFINITY;
        #pragma unroll
        for (int o = 4; o; o >>= 1) v = fmaxf(v, __shfl_xor_sync(0xffffffffu, v, o));
        if (tid == 0) s_bcast = v;
    }
    __syncthreads();
    const float M = s_bcast;
    __syncthreads();

    // exp + block sum
    float sum = 0.f;
    for (int idx = tid; idx < cnt; idx += 256) {
        float e = expf(s_log[idx] - M);
        s_log[idx] = e;           // keep unnormalized weights
        sum += e;
    }
    #pragma unroll
    for (int o = 16; o; o >>= 1) sum += __shfl_xor_sync(0xffffffffu, sum, o);
    if (lane == 0) s_red[wid] = sum;
    __syncthreads();
    if (tid < 32) {
        float v = (tid < 8) ? s_red[tid] : 0.f;
        #pragma unroll
        for (int o = 4; o; o >>= 1) v += __shfl_xor_sync(0xffffffffu, v, o);
        if (tid == 0) s_bcast = v;
    }
    __syncthreads();
    const float invS = 1.f / s_bcast;
    __syncthreads();

    // -------- Phase C: weighted sum -> att_out[b] --------
    for (int d = tid; d < D; d += 256) {
        float acc = 0.f;
        const float* p = repre + (size_t)start * D + d;
        for (int row = 0; row < cnt; ++row)
            acc = fmaf(s_log[row], p[(size_t)row * D], acc);
        att_out[(size_t)b * D + d] = acc * invS;
    }
}

// ---------------------------------------------------------------------------
// Kernel 2: logits = att (NB x 690) @ relation^T (690 x 53) + bias
// Tiled fp32 GEMM: CTA computes 64 bags x 64 cols (only 53 valid),
// 256 threads, 4x4 register tile each, BK = 64.
// ---------------------------------------------------------------------------
#define BK 64
__global__ __launch_bounds__(256)
void bag_logits_gemm(const float* __restrict__ att,
                     const float* __restrict__ rel,
                     const float* __restrict__ bias,
                     float* __restrict__ out,
                     int num_bags)
{
    __shared__ float As[64][BK + 1];
    __shared__ float Bs[64][BK + 1];

    const int tid  = threadIdx.x;
    const int tx   = tid & 15;     // n dim
    const int ty   = tid >> 4;     // m dim
    const int bRow = blockIdx.x * 64;

    float acc[4][4];
    #pragma unroll
    for (int i = 0; i < 4; ++i)
        #pragma unroll
        for (int j = 0; j < 4; ++j) acc[i][j] = 0.f;

    const int nChunks = (D + BK - 1) / BK;   // 11
    for (int t = 0; t < nChunks; ++t) {
        const int k0 = t * BK;
        // load A tile (64 bags x BK), zero-pad OOB
        for (int idx = tid; idx < 64 * BK; idx += 256) {
            int r = idx >> 6, c = idx & (BK - 1);
            int bag = bRow + r, k = k0 + c;
            As[r][c] = (bag < num_bags && k < D) ? att[(size_t)bag * D + k] : 0.f;
        }
        // load B tile (64 rel-rows x BK), rows >= 53 zero
        for (int idx = tid; idx < 64 * BK; idx += 256) {
            int r = idx >> 6, c = idx & (BK - 1);
            int k = k0 + c;
            Bs[r][c] = (r < R && k < D) ? rel[(size_t)r * D + k] : 0.f;
        }
        __syncthreads();

        #pragma unroll 16
        for (int kk = 0; kk < BK; ++kk) {
            float a[4], bb[4];
            #pragma unroll
            for (int mm = 0; mm < 4; ++mm) a[mm] = As[ty + 16 * mm][kk];
            #pragma unroll
            for (int nn = 0; nn < 4; ++nn) bb[nn] = Bs[tx + 16 * nn][kk];
            #pragma unroll
            for (int mm = 0; mm < 4; ++mm)
                #pragma unroll
                for (int nn = 0; nn < 4; ++nn)
                    acc[mm][nn] = fmaf(a[mm], bb[nn], acc[mm][nn]);
        }
        __syncthreads();
    }

    #pragma unroll
    for (int mm = 0; mm < 4; ++mm) {
        int bag = bRow + ty + 16 * mm;
        if (bag >= num_bags) continue;
        #pragma unroll
        for (int nn = 0; nn < 4; ++nn) {
            int n = tx + 16 * nn;
            if (n < R)
                out[(size_t)bag * R + n] = acc[mm][nn] + bias[n];
        }
    }
}

extern "C" void kernel_launch(void* const* d_in, const int* in_sizes, int n_in,
                              void* d_out, int out_size)
{
    const float* repre  = (const float*)d_in[0];
    const float* rel    = (const float*)d_in[1];
    const float* bias   = (const float*)d_in[2];
    const int*   scope  = (const int*)d_in[3];
    const int*   labels = (const int*)d_in[4];
    float* out = (float*)d_out;

    const int num_bags = in_sizes[3] / 2;

    float* att;
    cudaGetSymbolAddress((void**)&att, g_att);

    bag_att_kernel<<<num_bags, 256>>>(repre, rel, scope, labels, att);

    int grid2 = (num_bags + 63) / 64;
    bag_logits_gemm<<<grid2, 256>>>(att, rel, bias, out, num_bags);
}